// round 6
// baseline (speedup 1.0000x reference)
#include <cuda_runtime.h>
#include <cstdint>
#include <cstddef>

#define Bb 32
#define Dd 256
#define Ll 4096
#define Kk 1024
#define Nn (Bb*Ll)            // 131072 rows
#define NDL (Bb*Dd*Ll)        // 33554432 z_q elements
#define TL 32                 // l-tile for gather
#define RESC_CAP 32768
#define TAU 4e-4f

__device__ int    g_idx[Nn];
__device__ float  g_enorm[Kk];
__device__ double g_acc;
__device__ float  g_bh[Kk * Dd];   // emb tf32-rounded
__device__ int    g_resc_cnt;
__device__ int    g_resc[RESC_CAP];

// ---------------------------------------------------------------------------
// helpers
// ---------------------------------------------------------------------------
__device__ __forceinline__ uint32_t smem_u32(const void* p) {
    uint32_t a;
    asm("{ .reg .u64 t; cvta.to.shared.u64 t, %1; cvt.u32.u64 %0, t; }"
        : "=r"(a) : "l"(p));
    return a;
}
__device__ __forceinline__ float tf32f(float x) {
    uint32_t r; asm("cvt.rna.tf32.f32 %0, %1;" : "=r"(r) : "f"(x));
    return __uint_as_float(r);
}
__device__ __forceinline__ void cp16(uint32_t dst, const void* src) {
    asm volatile("cp.async.cg.shared.global [%0], [%1], 16;"
                 :: "r"(dst), "l"(src) : "memory");
}
#define CP_COMMIT() asm volatile("cp.async.commit_group;" ::: "memory")
#define CP_WAIT0()  asm volatile("cp.async.wait_group 0;" ::: "memory")

__device__ __forceinline__ void mma8(float* c, const uint32_t* a,
                                     uint32_t b0, uint32_t b1) {
    asm volatile("mma.sync.aligned.m16n8k8.row.col.f32.tf32.tf32.f32 "
        "{%0,%1,%2,%3}, {%4,%5,%6,%7}, {%8,%9}, {%0,%1,%2,%3};"
        : "+f"(c[0]), "+f"(c[1]), "+f"(c[2]), "+f"(c[3])
        : "r"(a[0]), "r"(a[1]), "r"(a[2]), "r"(a[3]), "r"(b0), "r"(b1));
}

// ---------------------------------------------------------------------------
// smem layout (bytes)
// ---------------------------------------------------------------------------
#define AS_STRIDE 260
#define BS_STRIDE 36
#define SM_AS   0
#define SM_B    133120
#define B_BUF   18432                  // one 128x36-word tile
#define SM_EN   (SM_B + 2*B_BUF)       // 169984
#define SM_ZN   (SM_EN + 4096)         // 174080
#define SM_TOTAL (SM_ZN + 512)         // 174592

// ---------------------------------------------------------------------------
// prep: per-code squared norms + zero accumulators
// ---------------------------------------------------------------------------
__global__ void vq_prep_kernel(const float* __restrict__ emb) {
    int k = blockIdx.x * blockDim.x + threadIdx.x;
    if (k == 0) { g_acc = 0.0; g_resc_cnt = 0; }
    if (k < Kk) {
        const float* row = emb + (size_t)k * Dd;
        float s = 0.f;
        #pragma unroll 8
        for (int d = 0; d < Dd; d++) { float v = row[d]; s += v * v; }
        g_enorm[k] = s;
    }
}

// round emb to tf32 once (reused by all 1024 score CTAs)
__global__ void vq_split_kernel(const float* __restrict__ emb) {
    int i = blockIdx.x * blockDim.x + threadIdx.x;
    if (i < Kk * Dd) g_bh[i] = tf32f(emb[i]);
}

// ---------------------------------------------------------------------------
// scores stage 1: plain-tf32 mma.sync GEMM (128 rows x 1024 codes per CTA)
// + fused argmin with second-best tracking; near-ties go to rescue list
// ---------------------------------------------------------------------------
__global__ void __launch_bounds__(256, 1)
vq_scores_kernel(const float* __restrict__ z) {
    extern __shared__ char smem[];
    const uint32_t sb = smem_u32(smem);
    float*    As   = (float*)(smem + SM_AS);
    float*    s_en = (float*)(smem + SM_EN);
    float*    s_zn = (float*)(smem + SM_ZN);

    const int tid   = threadIdx.x;
    const int wid   = tid >> 5;
    const int lane  = tid & 31;
    const int g     = lane >> 2;       // groupID
    const int tig   = lane & 3;        // thread-in-group
    const int warpM = wid & 3;
    const int warpN = wid >> 2;
    const int m0    = warpM * 32;
    const int n0w   = warpN * 64;

    const int row0 = blockIdx.x * 128;
    const int b    = row0 >> 12;
    const int l0   = row0 & (Ll - 1);
    const float* zb = z + (size_t)b * Dd * Ll + l0;

    // stage z tile, tf32-rounded once: As[l][d]
    for (int i = tid; i < 128 * Dd; i += 256) {
        int d = i >> 7, l = i & 127;
        As[l * AS_STRIDE + d] = tf32f(zb[(size_t)d * Ll + l]);
    }
    for (int i = tid; i < Kk; i += 256) s_en[i] = g_enorm[i];
    // per-row ||z||^2 from EXACT z (sequential fp32, reference-like)
    if (tid < 128) {
        float s = 0.f;
        #pragma unroll 8
        for (int d = 0; d < Dd; d++) { float v = zb[(size_t)d * Ll + tid]; s += v * v; }
        s_zn[tid] = s;
    }
    __syncthreads();

    // per-thread cp.async target offsets (4 float4 per tile)
    int cn[4], cj[4];
    uint32_t cso[4];
    #pragma unroll
    for (int q = 0; q < 4; q++) {
        int f4i = q * 256 + tid;
        cn[q]  = f4i >> 3;
        cj[q]  = (f4i & 7) * 4;
        cso[q] = (uint32_t)(cn[q] * BS_STRIDE + cj[q]) * 4u;
    }

    float zn_t[4];
    #pragma unroll
    for (int s = 0; s < 4; s++)
        zn_t[s] = s_zn[m0 + ((s >> 1) * 16) + ((s & 1) * 8) + g];

    float b1v[4], b2v[4];
    int   b1i[4];
    #pragma unroll
    for (int s = 0; s < 4; s++) { b1v[s] = 3.4e38f; b2v[s] = 3.4e38f; b1i[s] = 0; }

    #pragma unroll 1
    for (int nc = 0; nc < 8; nc++) {
        float acc[2][8][4];
        #pragma unroll
        for (int mt = 0; mt < 2; mt++)
            #pragma unroll
            for (int nt = 0; nt < 8; nt++)
                #pragma unroll
                for (int r = 0; r < 4; r++) acc[mt][nt][r] = 0.f;

        // prefetch d-chunk 0 into buffer 0
        #pragma unroll
        for (int q = 0; q < 4; q++)
            cp16(sb + SM_B + cso[q], g_bh + (size_t)(nc * 128 + cn[q]) * Dd + cj[q]);
        CP_COMMIT();

        #pragma unroll 1
        for (int dc = 0; dc < 8; dc++) {
            const int buf = dc & 1;
            CP_WAIT0();
            __syncthreads();
            if (dc < 7) {
                const uint32_t bdst = sb + SM_B + (uint32_t)((buf ^ 1) * B_BUF);
                #pragma unroll
                for (int q = 0; q < 4; q++)
                    cp16(bdst + cso[q],
                         g_bh + (size_t)(nc * 128 + cn[q]) * Dd + (dc + 1) * 32 + cj[q]);
                CP_COMMIT();
            }

            const uint32_t* Bh = (const uint32_t*)(smem + SM_B + buf * B_BUF);

            #pragma unroll
            for (int ks = 0; ks < 4; ks++) {
                const int dcol = dc * 32 + ks * 8 + tig;
                uint32_t ah[2][4];
                #pragma unroll
                for (int mt = 0; mt < 2; mt++) {
                    const uint32_t* ap =
                        (const uint32_t*)(As + (m0 + mt * 16 + g) * AS_STRIDE + dcol);
                    ah[mt][0] = ap[0];
                    ah[mt][1] = ap[8 * AS_STRIDE];
                    ah[mt][2] = ap[4];
                    ah[mt][3] = ap[8 * AS_STRIDE + 4];
                }
                #pragma unroll
                for (int nt = 0; nt < 8; nt++) {
                    const int n = n0w + nt * 8 + g;
                    const int bo = n * BS_STRIDE + ks * 8 + tig;
                    uint32_t bh0 = Bh[bo], bh1 = Bh[bo + 4];
                    mma8(acc[0][nt], ah[0], bh0, bh1);
                    mma8(acc[1][nt], ah[1], bh0, bh1);
                }
            }
        }
        __syncthreads();   // mma LDS done before next nc's cp.async overwrites

        // epilogue: dist + best/second-best, ascending k per slot
        #pragma unroll
        for (int nt = 0; nt < 8; nt++) {
            const int kb = nc * 128 + n0w + nt * 8 + 2 * tig;
            const float e0 = s_en[kb], e1 = s_en[kb + 1];
            #pragma unroll
            for (int mt = 0; mt < 2; mt++) {
                const int s0 = 2 * mt, s1 = 2 * mt + 1;
                float d0 = (zn_t[s0] + e0) - 2.f * acc[mt][nt][0];
                float d1 = (zn_t[s0] + e1) - 2.f * acc[mt][nt][1];
                float d2 = (zn_t[s1] + e0) - 2.f * acc[mt][nt][2];
                float d3 = (zn_t[s1] + e1) - 2.f * acc[mt][nt][3];
                if (d0 < b1v[s0]) { b2v[s0] = b1v[s0]; b1v[s0] = d0; b1i[s0] = kb; }
                else if (d0 < b2v[s0]) b2v[s0] = d0;
                if (d1 < b1v[s0]) { b2v[s0] = b1v[s0]; b1v[s0] = d1; b1i[s0] = kb + 1; }
                else if (d1 < b2v[s0]) b2v[s0] = d1;
                if (d2 < b1v[s1]) { b2v[s1] = b1v[s1]; b1v[s1] = d2; b1i[s1] = kb; }
                else if (d2 < b2v[s1]) b2v[s1] = d2;
                if (d3 < b1v[s1]) { b2v[s1] = b1v[s1]; b1v[s1] = d3; b1i[s1] = kb + 1; }
                else if (d3 < b2v[s1]) b2v[s1] = d3;
            }
        }
    }

    // reduce across tig quad (same rows), tracking best + second-best
    #pragma unroll
    for (int s = 0; s < 4; s++) {
        #pragma unroll
        for (int off = 1; off <= 2; off <<= 1) {
            float o1v = __shfl_xor_sync(0xffffffffu, b1v[s], off);
            int   o1i = __shfl_xor_sync(0xffffffffu, b1i[s], off);
            float o2v = __shfl_xor_sync(0xffffffffu, b2v[s], off);
            if (o1v < b1v[s] || (o1v == b1v[s] && o1i < b1i[s])) {
                b2v[s] = fminf(b1v[s], o2v);
                b1v[s] = o1v; b1i[s] = o1i;
            } else {
                b2v[s] = fminf(o1v, b2v[s]);
            }
        }
    }

    // merge the two warpN halves via smem (reuse B buffer region)
    float* mv  = (float*)(smem + SM_B);
    int*   mi  = (int*)(smem + SM_B + 512);
    float* mv2 = (float*)(smem + SM_B + 1024);
    __syncthreads();
    if (warpN == 1 && tig == 0) {
        #pragma unroll
        for (int s = 0; s < 4; s++) {
            int row = m0 + (s >> 1) * 16 + (s & 1) * 8 + g;
            mv[row] = b1v[s]; mi[row] = b1i[s]; mv2[row] = b2v[s];
        }
    }
    __syncthreads();
    if (warpN == 0 && tig == 0) {
        #pragma unroll
        for (int s = 0; s < 4; s++) {
            int row = m0 + (s >> 1) * 16 + (s & 1) * 8 + g;
            float o1v = mv[row]; int o1i = mi[row]; float o2v = mv2[row];
            float v1 = b1v[s]; int i1 = b1i[s]; float v2 = b2v[s];
            if (o1v < v1 || (o1v == v1 && o1i < i1)) {
                v2 = fminf(v1, o2v); v1 = o1v; i1 = o1i;
            } else {
                v2 = fminf(o1v, v2);
            }
            g_idx[row0 + row] = i1;
            if (v2 - v1 < TAU) {
                int p = atomicAdd(&g_resc_cnt, 1);
                if (p < RESC_CAP) g_resc[p] = row0 + row;
            }
        }
    }
}

// ---------------------------------------------------------------------------
// rescue: exact sequential-fp32 recompute for near-tie rows (reference-order
// arithmetic; identical to the R1 kernel that matched the reference)
// ---------------------------------------------------------------------------
__global__ void __launch_bounds__(128)
vq_rescue_kernel(const float* __restrict__ z, const float* __restrict__ emb) {
    __shared__ float zrow[Dd];
    __shared__ float sv[128];
    __shared__ int   si[128];

    int cnt = g_resc_cnt;
    if (cnt > RESC_CAP) cnt = RESC_CAP;
    if ((int)blockIdx.x >= cnt) return;

    const int tid = threadIdx.x;
    const int row = g_resc[blockIdx.x];
    const int b   = row >> 12;
    const int l   = row & (Ll - 1);
    const float* zb = z + (size_t)b * Dd * Ll + l;

    for (int d = tid; d < Dd; d += 128) zrow[d] = zb[(size_t)d * Ll];
    __syncthreads();

    float zn = 0.f;
    #pragma unroll 8
    for (int d = 0; d < Dd; d++) { float v = zrow[d]; zn += v * v; }

    float bv = 3.4e38f;
    int   bi = 0;
    for (int k = tid; k < Kk; k += 128) {      // ascending k per thread
        const float* e = emb + (size_t)k * Dd;
        float acc = 0.f;
        #pragma unroll 8
        for (int d = 0; d < Dd; d++) acc = fmaf(zrow[d], e[d], acc);
        float dist = (zn + g_enorm[k]) - 2.0f * acc;
        if (dist < bv) { bv = dist; bi = k; }
    }

    sv[tid] = bv; si[tid] = bi;
    __syncthreads();
    for (int off = 64; off; off >>= 1) {
        if (tid < off) {
            float ov = sv[tid + off]; int oi = si[tid + off];
            if (ov < sv[tid] || (ov == sv[tid] && oi < si[tid])) {
                sv[tid] = ov; si[tid] = oi;
            }
        }
        __syncthreads();
    }
    if (tid == 0) g_idx[row] = si[0];
}

// ---------------------------------------------------------------------------
// gather: z_q_st = embedding[idx] scattered to (B,D,L); fused sum((z-q)^2)
// ---------------------------------------------------------------------------
__global__ void __launch_bounds__(256)
vq_gather_kernel(const float* __restrict__ z, const float* __restrict__ emb,
                 float* __restrict__ out) {
    __shared__ float q[TL][Dd + 1];
    __shared__ int   idxs[TL];
    __shared__ float wsum[8];

    const int tid = threadIdx.x;
    const int t   = blockIdx.x;
    const int b   = t >> 7;
    const int l0  = (t & 127) * TL;
    const int rbase = b * Ll + l0;

    if (tid < TL) idxs[tid] = g_idx[rbase + tid];
    __syncthreads();

    for (int i = tid; i < TL * Dd; i += 256) {
        int r = i >> 8, d = i & 255;
        q[r][d] = emb[(size_t)idxs[r] * Dd + d];
    }
    __syncthreads();

    float lsum = 0.f;
    const float* zb = z   + (size_t)b * Dd * Ll + l0;
    float*       ob = out + (size_t)b * Dd * Ll + l0;
    for (int i = tid; i < Dd * TL; i += 256) {
        int d = i >> 5, lr = i & 31;
        float v  = q[lr][d];
        float ze = zb[(size_t)d * Ll + lr];
        ob[(size_t)d * Ll + lr] = v;
        float df = ze - v;
        lsum += df * df;
    }

    #pragma unroll
    for (int off = 16; off; off >>= 1)
        lsum += __shfl_xor_sync(0xffffffffu, lsum, off);
    if ((tid & 31) == 0) wsum[tid >> 5] = lsum;
    __syncthreads();
    if (tid == 0) {
        float s = 0.f;
        #pragma unroll
        for (int w = 0; w < 8; w++) s += wsum[w];
        atomicAdd(&g_acc, (double)s);
    }
}

// ---------------------------------------------------------------------------
__global__ void vq_tail_kernel(float* __restrict__ out) {
    int i = blockIdx.x * blockDim.x + threadIdx.x;
    if (i < Nn) out[NDL + i] = (float)g_idx[i];
}

__global__ void vq_loss_kernel(float* __restrict__ out) {
    double mse = g_acc / (double)NDL;
    out[NDL + Nn + 0] = (float)(1.25 * mse);
    out[NDL + Nn + 1] = (float)mse;
    out[NDL + Nn + 2] = (float)(0.25 * mse);
}

// ---------------------------------------------------------------------------
extern "C" void kernel_launch(void* const* d_in, const int* in_sizes, int n_in,
                              void* d_out, int out_size) {
    const float* z   = (const float*)d_in[0];
    const float* emb = (const float*)d_in[1];
    if (n_in >= 2 && in_sizes[0] == Kk * Dd && in_sizes[1] == NDL) {
        emb = (const float*)d_in[0];
        z   = (const float*)d_in[1];
    }
    float* out = (float*)d_out;

    cudaFuncSetAttribute(vq_scores_kernel,
                         cudaFuncAttributeMaxDynamicSharedMemorySize, SM_TOTAL);

    vq_prep_kernel<<<(Kk + 255) / 256, 256>>>(emb);
    vq_split_kernel<<<(Kk * Dd + 255) / 256, 256>>>(emb);
    vq_scores_kernel<<<Nn / 128, 256, SM_TOTAL>>>(z);
    vq_rescue_kernel<<<RESC_CAP, 128>>>(z, emb);
    vq_gather_kernel<<<Nn / TL, 256>>>(z, emb, out);
    if (out_size >= NDL + Nn)
        vq_tail_kernel<<<(Nn + 255) / 256, 256>>>(out);
    if (out_size >= NDL + Nn + 3)
        vq_loss_kernel<<<1, 1>>>(out);
}

// round 7
// speedup vs baseline: 3.1196x; 3.1196x over previous
#include <cuda_runtime.h>
#include <cstdint>
#include <cstddef>

#define Bb 32
#define Dd 256
#define Ll 4096
#define Kk 1024
#define Nn (Bb*Ll)            // 131072 rows
#define NDL (Bb*Dd*Ll)        // 33554432 z_q elements
#define TL 32                 // l-tile for gather

__device__ int    g_idx[Nn];
__device__ float  g_enorm[Kk];
__device__ double g_acc;

// ---------------------------------------------------------------------------
// smem layout (bytes): zs[256][132] | es[256][68] | en[1024] | zn[128]
// ---------------------------------------------------------------------------
#define ZST 132
#define EST 68
#define SM_ZS 0
#define SM_ES (256*ZST*4)            // 135168
#define SM_EN (SM_ES + 256*EST*4)    // 204800
#define SM_ZN (SM_EN + 4096)         // 208896
#define SM_TOTAL (SM_ZN + 512)       // 209408

// ---------------------------------------------------------------------------
// packed f32x2 helpers
// ---------------------------------------------------------------------------
__device__ __forceinline__ void fma_x2(uint64_t& c, uint64_t a, uint64_t b) {
    asm("fma.rn.f32x2 %0, %1, %2, %0;" : "+l"(c) : "l"(a), "l"(b));
}
__device__ __forceinline__ uint64_t dup_x2(float x) {
    uint64_t r;
    asm("mov.b64 %0, {%1, %1};" : "=l"(r) : "f"(x));
    return r;
}
__device__ __forceinline__ void unpack_x2(float& lo, float& hi, uint64_t v) {
    asm("mov.b64 {%0, %1}, %2;" : "=f"(lo), "=f"(hi) : "l"(v));
}
__device__ __forceinline__ void lds_v2u64(uint64_t& a, uint64_t& b, const void* p) {
    asm volatile("ld.shared.v2.b64 {%0, %1}, [%2];"
                 : "=l"(a), "=l"(b) : "l"(__cvta_generic_to_shared(p)));
}
__device__ __forceinline__ void lds_v4f32(float& a, float& b, float& c, float& d,
                                          const void* p) {
    asm volatile("ld.shared.v4.f32 {%0, %1, %2, %3}, [%4];"
                 : "=f"(a), "=f"(b), "=f"(c), "=f"(d)
                 : "l"(__cvta_generic_to_shared(p)));
}

// ---------------------------------------------------------------------------
// prep: per-code squared norms + zero loss accumulator
// ---------------------------------------------------------------------------
__global__ void vq_prep_kernel(const float* __restrict__ emb) {
    int k = blockIdx.x * blockDim.x + threadIdx.x;
    if (k == 0) g_acc = 0.0;
    if (k < Kk) {
        const float* row = emb + (size_t)k * Dd;
        float s = 0.f;
        #pragma unroll 8
        for (int d = 0; d < Dd; d++) { float v = row[d]; s += v * v; }
        g_enorm[k] = s;
    }
}

// ---------------------------------------------------------------------------
// scores: exact fp32 distances via packed fma.rn.f32x2 (FFMA2), fused argmin.
// CTA = 128 rows x 1024 codes; thread = 8 rows (4 f32x2 pairs) x 8 codes.
// Arithmetic is bit-identical to the R1 reference-matching kernel:
//   acc = sequential fmaf over d (each packed half is one IEEE fp32 chain),
//   dist = (||z||^2 + ||e||^2) - 2*acc, ascending-k strict-< argmin.
// ---------------------------------------------------------------------------
__global__ void __launch_bounds__(128, 1)
vq_scores_f32x2(const float* __restrict__ z, const float* __restrict__ emb) {
    extern __shared__ char smem[];
    float* zs   = (float*)(smem + SM_ZS);   // [256][ZST]  z transposed: [d][row]
    float* es   = (float*)(smem + SM_ES);   // [256][EST]  e transposed: [d][k]
    float* s_en = (float*)(smem + SM_EN);
    float* s_zn = (float*)(smem + SM_ZN);

    const int tid = threadIdx.x;
    const int cg  = tid & 7;        // code-group: 8 codes each
    const int rg  = tid >> 3;       // row-group: 8 rows each (16 groups)
    const int r0  = rg * 8;
    const int k0c = cg * 8;

    const int row0 = blockIdx.x * 128;
    const int b    = row0 >> 12;
    const int l0   = row0 & (Ll - 1);
    const float* zb = z + (size_t)b * Dd * Ll + l0;

    // stage z transposed: zs[d][l]  (coalesced LDG, conflict-free STS)
    #pragma unroll 4
    for (int d = 0; d < Dd; d++)
        zs[d * ZST + tid] = zb[(size_t)d * Ll + tid];
    for (int i = tid; i < Kk; i += 128) s_en[i] = g_enorm[i];
    __syncthreads();

    // per-row ||z||^2: sequential fp32 chain over ascending d (reference-like)
    {
        float s = 0.f;
        #pragma unroll 8
        for (int d = 0; d < Dd; d++) { float v = zs[d * ZST + tid]; s += v * v; }
        s_zn[tid] = s;
    }
    __syncthreads();

    float zr[8];
    #pragma unroll
    for (int j = 0; j < 8; j++) zr[j] = s_zn[r0 + j];

    float bv[8];
    int   bi[8];
    #pragma unroll
    for (int j = 0; j < 8; j++) { bv[j] = 3.4e38f; bi[j] = 0; }

    #pragma unroll 1
    for (int kt = 0; kt < 16; kt++) {
        // stage 64-code tile transposed: es[d][k]  (coalesced LDG)
        const float* et = emb + (size_t)kt * 64 * Dd;
        #pragma unroll 2
        for (int i = tid; i < 64 * Dd; i += 128) {
            int d = i & 255, k = i >> 8;
            es[d * EST + k] = et[(size_t)k * Dd + d];
        }
        __syncthreads();

        uint64_t acc[4][8];
        #pragma unroll
        for (int p = 0; p < 4; p++)
            #pragma unroll
            for (int c = 0; c < 8; c++) acc[p][c] = 0ull;

        #pragma unroll 4
        for (int d = 0; d < Dd; d++) {
            uint64_t zp[4];
            lds_v2u64(zp[0], zp[1], zs + d * ZST + r0);
            lds_v2u64(zp[2], zp[3], zs + d * ZST + r0 + 4);
            float e[8];
            lds_v4f32(e[0], e[1], e[2], e[3], es + d * EST + k0c);
            lds_v4f32(e[4], e[5], e[6], e[7], es + d * EST + k0c + 4);
            #pragma unroll
            for (int c = 0; c < 8; c++) {
                uint64_t eb = dup_x2(e[c]);
                fma_x2(acc[0][c], zp[0], eb);
                fma_x2(acc[1][c], zp[1], eb);
                fma_x2(acc[2][c], zp[2], eb);
                fma_x2(acc[3][c], zp[3], eb);
            }
        }

        // epilogue: dist + argmin, ascending k (kt outer asc, c inner asc)
        #pragma unroll
        for (int c = 0; c < 8; c++) {
            const int k = kt * 64 + k0c + c;
            const float en = s_en[k];
            #pragma unroll
            for (int p = 0; p < 4; p++) {
                float a0, a1;
                unpack_x2(a0, a1, acc[p][c]);
                const int j0 = 2 * p, j1 = 2 * p + 1;
                float d0 = (zr[j0] + en) - 2.0f * a0;
                float d1 = (zr[j1] + en) - 2.0f * a1;
                if (d0 < bv[j0]) { bv[j0] = d0; bi[j0] = k; }
                if (d1 < bv[j1]) { bv[j1] = d1; bi[j1] = k; }
            }
        }
        __syncthreads();   // LDS reads done before next tile restages es
    }

    // merge across the 8 code-lanes of each row-group (width-8 shuffles),
    // tie -> lower index
    #pragma unroll
    for (int off = 4; off; off >>= 1) {
        #pragma unroll
        for (int j = 0; j < 8; j++) {
            float ov = __shfl_down_sync(0xffffffffu, bv[j], off, 8);
            int   oi = __shfl_down_sync(0xffffffffu, bi[j], off, 8);
            if (ov < bv[j] || (ov == bv[j] && oi < bi[j])) {
                bv[j] = ov; bi[j] = oi;
            }
        }
    }
    if (cg == 0) {
        #pragma unroll
        for (int j = 0; j < 8; j++)
            g_idx[row0 + r0 + j] = bi[j];
    }
}

// ---------------------------------------------------------------------------
// gather: z_q_st = embedding[idx] scattered to (B,D,L); fused sum((z-q)^2)
// ---------------------------------------------------------------------------
__global__ void __launch_bounds__(256)
vq_gather_kernel(const float* __restrict__ z, const float* __restrict__ emb,
                 float* __restrict__ out) {
    __shared__ float q[TL][Dd + 1];
    __shared__ int   idxs[TL];
    __shared__ float wsum[8];

    const int tid = threadIdx.x;
    const int t   = blockIdx.x;
    const int b   = t >> 7;
    const int l0  = (t & 127) * TL;
    const int rbase = b * Ll + l0;

    if (tid < TL) idxs[tid] = g_idx[rbase + tid];
    __syncthreads();

    for (int i = tid; i < TL * Dd; i += 256) {
        int r = i >> 8, d = i & 255;
        q[r][d] = emb[(size_t)idxs[r] * Dd + d];
    }
    __syncthreads();

    float lsum = 0.f;
    const float* zb = z   + (size_t)b * Dd * Ll + l0;
    float*       ob = out + (size_t)b * Dd * Ll + l0;
    for (int i = tid; i < Dd * TL; i += 256) {
        int d = i >> 5, lr = i & 31;
        float v  = q[lr][d];
        float ze = zb[(size_t)d * Ll + lr];
        ob[(size_t)d * Ll + lr] = v;
        float df = ze - v;
        lsum += df * df;
    }

    #pragma unroll
    for (int off = 16; off; off >>= 1)
        lsum += __shfl_xor_sync(0xffffffffu, lsum, off);
    if ((tid & 31) == 0) wsum[tid >> 5] = lsum;
    __syncthreads();
    if (tid == 0) {
        float s = 0.f;
        #pragma unroll
        for (int w = 0; w < 8; w++) s += wsum[w];
        atomicAdd(&g_acc, (double)s);
    }
}

// ---------------------------------------------------------------------------
__global__ void vq_tail_kernel(float* __restrict__ out) {
    int i = blockIdx.x * blockDim.x + threadIdx.x;
    if (i < Nn) out[NDL + i] = (float)g_idx[i];
}

__global__ void vq_loss_kernel(float* __restrict__ out) {
    double mse = g_acc / (double)NDL;
    out[NDL + Nn + 0] = (float)(1.25 * mse);
    out[NDL + Nn + 1] = (float)mse;
    out[NDL + Nn + 2] = (float)(0.25 * mse);
}

// ---------------------------------------------------------------------------
extern "C" void kernel_launch(void* const* d_in, const int* in_sizes, int n_in,
                              void* d_out, int out_size) {
    const float* z   = (const float*)d_in[0];
    const float* emb = (const float*)d_in[1];
    if (n_in >= 2 && in_sizes[0] == Kk * Dd && in_sizes[1] == NDL) {
        emb = (const float*)d_in[0];
        z   = (const float*)d_in[1];
    }
    float* out = (float*)d_out;

    cudaFuncSetAttribute(vq_scores_f32x2,
                         cudaFuncAttributeMaxDynamicSharedMemorySize, SM_TOTAL);

    vq_prep_kernel<<<(Kk + 255) / 256, 256>>>(emb);
    vq_scores_f32x2<<<Nn / 128, 128, SM_TOTAL>>>(z, emb);
    vq_gather_kernel<<<Nn / TL, 256>>>(z, emb, out);
    if (out_size >= NDL + Nn)
        vq_tail_kernel<<<(Nn + 255) / 256, 256>>>(out);
    if (out_size >= NDL + Nn + 3)
        vq_loss_kernel<<<1, 1>>>(out);
}

// round 9
// speedup vs baseline: 4.5386x; 1.4549x over previous
#include <cuda_runtime.h>
#include <cstdint>
#include <cstddef>

#define Bb 32
#define Dd 256
#define Ll 4096
#define Kk 1024
#define Nn (Bb*Ll)            // 131072 rows
#define NDL (Bb*Dd*Ll)        // 33554432 z_q elements
#define TL 32                 // l-tile for gather

__device__ int    g_idx[Nn];
__device__ float  g_enorm[Kk];
__device__ double g_acc;

// ---------------------------------------------------------------------------
// smem layout (bytes): zs[256][132] | es[128][132] | en[1024] | zn[128]
// ---------------------------------------------------------------------------
#define ZST 132
#define EST 132
#define SM_ZS 0
#define SM_ES (256*ZST*4)              // 135168
#define SM_EN (SM_ES + 128*EST*4)      // 202752
#define SM_ZN (SM_EN + 4096)           // 206848
#define SM_TOTAL (SM_ZN + 512)         // 207360

// ---------------------------------------------------------------------------
// packed f32x2 helpers
// ---------------------------------------------------------------------------
__device__ __forceinline__ void fma_x2(uint64_t& c, uint64_t a, uint64_t b) {
    asm("fma.rn.f32x2 %0, %1, %2, %0;" : "+l"(c) : "l"(a), "l"(b));
}
__device__ __forceinline__ uint64_t dup_x2(float x) {
    uint64_t r;
    asm("mov.b64 %0, {%1, %1};" : "=l"(r) : "f"(x));
    return r;
}
__device__ __forceinline__ void unpack_x2(float& lo, float& hi, uint64_t v) {
    asm("mov.b64 {%0, %1}, %2;" : "=f"(lo), "=f"(hi) : "l"(v));
}
__device__ __forceinline__ void lds_v2u64(uint64_t& a, uint64_t& b, const void* p) {
    asm volatile("ld.shared.v2.b64 {%0, %1}, [%2];"
                 : "=l"(a), "=l"(b) : "l"(__cvta_generic_to_shared(p)));
}
__device__ __forceinline__ void lds_v4f32(float& a, float& b, float& c, float& d,
                                          const void* p) {
    asm volatile("ld.shared.v4.f32 {%0, %1, %2, %3}, [%4];"
                 : "=f"(a), "=f"(b), "=f"(c), "=f"(d)
                 : "l"(__cvta_generic_to_shared(p)));
}

// ---------------------------------------------------------------------------
// prep: per-code squared norms + zero loss accumulator
// ---------------------------------------------------------------------------
__global__ void vq_prep_kernel(const float* __restrict__ emb) {
    int k = blockIdx.x * blockDim.x + threadIdx.x;
    if (k == 0) g_acc = 0.0;
    if (k < Kk) {
        const float* row = emb + (size_t)k * Dd;
        float s = 0.f;
        #pragma unroll 8
        for (int d = 0; d < Dd; d++) { float v = row[d]; s += v * v; }
        g_enorm[k] = s;
    }
}

// ---------------------------------------------------------------------------
// scores: exact fp32 distances via packed fma.rn.f32x2 (FFMA2), fused argmin.
// 512 threads; CTA = 128 rows x 1024 codes in 8 k-tiles of 128;
// thread = 8 rows (4 f32x2 pairs) x 4 codes.
// Arithmetic identical to the reference-matching R1/R7 kernels:
//   one sequential fp32 FMA chain over ascending d per (row, code),
//   dist = (||z||^2 + ||e||^2) - 2*acc, ascending-k strict-< argmin.
// ---------------------------------------------------------------------------
__global__ void __launch_bounds__(512, 1)
vq_scores_f32x2(const float* __restrict__ z, const float* __restrict__ emb) {
    extern __shared__ char smem[];
    float* zs   = (float*)(smem + SM_ZS);   // [256][ZST] z transposed: [d][row]
    float* es   = (float*)(smem + SM_ES);   // [128][EST] e chunk: [dd][k]
    float* s_en = (float*)(smem + SM_EN);
    float* s_zn = (float*)(smem + SM_ZN);

    const int tid  = threadIdx.x;
    const int lane = tid & 31;      // code-group: 4 codes each (k-tile = 128)
    const int rg   = tid >> 5;      // row-group (= warp): 8 rows each
    const int r0   = rg * 8;
    const int k0   = lane * 4;

    const int row0 = blockIdx.x * 128;
    const int b    = row0 >> 12;
    const int l0   = row0 & (Ll - 1);
    const float* zb = z + (size_t)b * Dd * Ll + l0;

    // stage z transposed zs[d][l]: coalesced float4 LDG, conflict-free STS.128
    #pragma unroll
    for (int i = 0; i < 16; i++) {
        int idx = i * 512 + tid;
        int l4  = (idx & 31) * 4;
        int d   = idx >> 5;
        float4 v = *(const float4*)&zb[(size_t)d * Ll + l4];
        *(float4*)&zs[d * ZST + l4] = v;
    }
    for (int i = tid; i < Kk; i += 512) s_en[i] = g_enorm[i];
    __syncthreads();

    // per-row ||z||^2: sequential fp32 chain over ascending d
    if (tid < 128) {
        float s = 0.f;
        #pragma unroll 8
        for (int d = 0; d < Dd; d++) { float v = zs[d * ZST + tid]; s += v * v; }
        s_zn[tid] = s;
    }
    __syncthreads();

    float zr[8];
    #pragma unroll
    for (int j = 0; j < 8; j++) zr[j] = s_zn[r0 + j];

    float bv[8];
    int   bi[8];
    #pragma unroll
    for (int j = 0; j < 8; j++) { bv[j] = 3.4e38f; bi[j] = 0; }

    #pragma unroll 1
    for (int kt = 0; kt < 8; kt++) {
        uint64_t acc[4][4];           // [row-pair][code]
        #pragma unroll
        for (int p = 0; p < 4; p++)
            #pragma unroll
            for (int c = 0; c < 4; c++) acc[p][c] = 0ull;

        #pragma unroll 1
        for (int chunk = 0; chunk < 2; chunk++) {
            __syncthreads();   // prior chunk's LDS reads done before restage
            // stage es[dd][k] for dd = 0..127 (global d = chunk*128+dd)
            #pragma unroll
            for (int i = 0; i < 8; i++) {
                int idx = i * 512 + tid;
                int k   = idx & 127;
                int d4  = (idx >> 7) * 4;
                float4 v = *(const float4*)&emb[(size_t)(kt * 128 + k) * Dd
                                                + chunk * 128 + d4];
                es[(d4 + 0) * EST + k] = v.x;
                es[(d4 + 1) * EST + k] = v.y;
                es[(d4 + 2) * EST + k] = v.z;
                es[(d4 + 3) * EST + k] = v.w;
            }
            __syncthreads();

            const float* zcol = zs + chunk * 128 * ZST;
            #pragma unroll 2
            for (int dd = 0; dd < 128; dd++) {
                uint64_t zp0, zp1, zp2, zp3;
                lds_v2u64(zp0, zp1, zcol + dd * ZST + r0);
                lds_v2u64(zp2, zp3, zcol + dd * ZST + r0 + 4);
                float e0, e1, e2, e3;
                lds_v4f32(e0, e1, e2, e3, es + dd * EST + k0);
                uint64_t eb0 = dup_x2(e0), eb1 = dup_x2(e1);
                uint64_t eb2 = dup_x2(e2), eb3 = dup_x2(e3);
                fma_x2(acc[0][0], zp0, eb0); fma_x2(acc[1][0], zp1, eb0);
                fma_x2(acc[2][0], zp2, eb0); fma_x2(acc[3][0], zp3, eb0);
                fma_x2(acc[0][1], zp0, eb1); fma_x2(acc[1][1], zp1, eb1);
                fma_x2(acc[2][1], zp2, eb1); fma_x2(acc[3][1], zp3, eb1);
                fma_x2(acc[0][2], zp0, eb2); fma_x2(acc[1][2], zp1, eb2);
                fma_x2(acc[2][2], zp2, eb2); fma_x2(acc[3][2], zp3, eb2);
                fma_x2(acc[0][3], zp0, eb3); fma_x2(acc[1][3], zp1, eb3);
                fma_x2(acc[2][3], zp2, eb3); fma_x2(acc[3][3], zp3, eb3);
            }
        }

        // epilogue: dist + argmin, ascending k (kt asc outer, c asc inner)
        #pragma unroll
        for (int c = 0; c < 4; c++) {
            const int k = kt * 128 + k0 + c;
            const float en = s_en[k];
            #pragma unroll
            for (int p = 0; p < 4; p++) {
                float a0, a1;
                unpack_x2(a0, a1, acc[p][c]);
                const int j0 = 2 * p, j1 = 2 * p + 1;
                float d0 = (zr[j0] + en) - 2.0f * a0;
                float d1 = (zr[j1] + en) - 2.0f * a1;
                if (d0 < bv[j0]) { bv[j0] = d0; bi[j0] = k; }
                if (d1 < bv[j1]) { bv[j1] = d1; bi[j1] = k; }
            }
        }
    }

    // merge across the 32 code-lanes of this row-group; tie -> lower index
    #pragma unroll
    for (int off = 16; off; off >>= 1) {
        #pragma unroll
        for (int j = 0; j < 8; j++) {
            float ov = __shfl_down_sync(0xffffffffu, bv[j], off);
            int   oi = __shfl_down_sync(0xffffffffu, bi[j], off);
            if (ov < bv[j] || (ov == bv[j] && oi < bi[j])) {
                bv[j] = ov; bi[j] = oi;
            }
        }
    }
    if (lane == 0) {
        #pragma unroll
        for (int j = 0; j < 8; j++)
            g_idx[row0 + r0 + j] = bi[j];
    }
}

// ---------------------------------------------------------------------------
// gather: z_q_st = embedding[idx] scattered to (B,D,L); fused sum((z-q)^2)
// ---------------------------------------------------------------------------
__global__ void __launch_bounds__(256)
vq_gather_kernel(const float* __restrict__ z, const float* __restrict__ emb,
                 float* __restrict__ out) {
    __shared__ float q[TL][Dd + 1];
    __shared__ int   idxs[TL];
    __shared__ float wsum[8];

    const int tid = threadIdx.x;
    const int t   = blockIdx.x;
    const int b   = t >> 7;
    const int l0  = (t & 127) * TL;
    const int rbase = b * Ll + l0;

    if (tid < TL) idxs[tid] = g_idx[rbase + tid];
    __syncthreads();

    for (int i = tid; i < TL * Dd; i += 256) {
        int r = i >> 8, d = i & 255;
        q[r][d] = emb[(size_t)idxs[r] * Dd + d];
    }
    __syncthreads();

    float lsum = 0.f;
    const float* zb = z   + (size_t)b * Dd * Ll + l0;
    float*       ob = out + (size_t)b * Dd * Ll + l0;
    for (int i = tid; i < Dd * TL; i += 256) {
        int d = i >> 5, lr = i & 31;
        float v  = q[lr][d];
        float ze = zb[(size_t)d * Ll + lr];
        ob[(size_t)d * Ll + lr] = v;
        float df = ze - v;
        lsum += df * df;
    }

    #pragma unroll
    for (int off = 16; off; off >>= 1)
        lsum += __shfl_xor_sync(0xffffffffu, lsum, off);
    if ((tid & 31) == 0) wsum[tid >> 5] = lsum;
    __syncthreads();
    if (tid == 0) {
        float s = 0.f;
        #pragma unroll
        for (int w = 0; w < 8; w++) s += wsum[w];
        atomicAdd(&g_acc, (double)s);
    }
}

// ---------------------------------------------------------------------------
__global__ void vq_tail_kernel(float* __restrict__ out) {
    int i = blockIdx.x * blockDim.x + threadIdx.x;
    if (i < Nn) out[NDL + i] = (float)g_idx[i];
}

__global__ void vq_loss_kernel(float* __restrict__ out) {
    double mse = g_acc / (double)NDL;
    out[NDL + Nn + 0] = (float)(1.25 * mse);
    out[NDL + Nn + 1] = (float)mse;
    out[NDL + Nn + 2] = (float)(0.25 * mse);
}

// ---------------------------------------------------------------------------
extern "C" void kernel_launch(void* const* d_in, const int* in_sizes, int n_in,
                              void* d_out, int out_size) {
    const float* z   = (const float*)d_in[0];
    const float* emb = (const float*)d_in[1];
    if (n_in >= 2 && in_sizes[0] == Kk * Dd && in_sizes[1] == NDL) {
        emb = (const float*)d_in[0];
        z   = (const float*)d_in[1];
    }
    float* out = (float*)d_out;

    cudaFuncSetAttribute(vq_scores_f32x2,
                         cudaFuncAttributeMaxDynamicSharedMemorySize, SM_TOTAL);

    vq_prep_kernel<<<(Kk + 255) / 256, 256>>>(emb);
    vq_scores_f32x2<<<Nn / 128, 512, SM_TOTAL>>>(z, emb);
    vq_gather_kernel<<<Nn / TL, 256>>>(z, emb, out);
    if (out_size >= NDL + Nn)
        vq_tail_kernel<<<(Nn + 255) / 256, 256>>>(out);
    if (out_size >= NDL + Nn + 3)
        vq_loss_kernel<<<1, 1>>>(out);
}